// round 3
// baseline (speedup 1.0000x reference)
#include <cuda_runtime.h>
#include <cuda_bf16.h>

#define DIM_IN   16
#define DIM_OUT  99
#define CHANNELS 128
#define MAX_NNZ  1024

// Scratch (allocation-free): CSR metadata sorted by output index m3.
// meta.x = (mu1<<4)|mu2, meta.y = float bits of cg
__device__ int2 g_meta[MAX_NNZ];
__device__ int  g_rowptr[DIM_OUT + 1];

// ---------------------------------------------------------------------------
// Preprocess: build CSR grouped by mu3. Deterministic (rank-based stable
// scatter, no reliance on atomic ordering for positions).
// ---------------------------------------------------------------------------
__global__ void tp_preprocess_kernel(const int* __restrict__ mu1,
                                     const int* __restrict__ mu2,
                                     const int* __restrict__ mu3,
                                     const float* __restrict__ cg,
                                     int nnz)
{
    __shared__ int mu3s[MAX_NNZ];
    __shared__ int cnt[DIM_OUT + 1];
    __shared__ int row_s[DIM_OUT + 1];

    int tid = threadIdx.x;
    for (int i = tid; i < DIM_OUT + 1; i += blockDim.x) cnt[i] = 0;
    for (int k = tid; k < nnz; k += blockDim.x) mu3s[k] = mu3[k];
    __syncthreads();

    for (int k = tid; k < nnz; k += blockDim.x) atomicAdd(&cnt[mu3s[k]], 1);
    __syncthreads();

    if (tid == 0) {
        int run = 0;
        for (int i = 0; i < DIM_OUT; i++) { row_s[i] = run; run += cnt[i]; }
        row_s[DIM_OUT] = run;
    }
    __syncthreads();

    for (int i = tid; i < DIM_OUT + 1; i += blockDim.x) g_rowptr[i] = row_s[i];

    // Stable rank within its m3 group: count earlier entries with same m3.
    for (int k = tid; k < nnz; k += blockDim.x) {
        int m = mu3s[k];
        int r = 0;
        for (int j = 0; j < k; j++) r += (mu3s[j] == m) ? 1 : 0;
        int pos = row_s[m] + r;
        g_meta[pos] = make_int2((mu1[k] << 4) | mu2[k], __float_as_int(cg[k]));
    }
}

// ---------------------------------------------------------------------------
// Main kernel: 128 threads = 2 edges per block; each thread owns 2 channels
// (float2) of one edge. x/y tiles staged in smem (conflict-free: consecutive
// channels -> consecutive banks). One accumulator register per m3, CSR order.
// ---------------------------------------------------------------------------
__global__ __launch_bounds__(128)
void tp_main_kernel(const float* __restrict__ x,
                    const float* __restrict__ y,
                    float* __restrict__ out,
                    int nnz)
{
    __shared__ __align__(16) float xs[2 * DIM_IN * CHANNELS];  // 16 KB
    __shared__ __align__(16) float ys[2 * DIM_IN * CHANNELS];  // 16 KB
    __shared__ int2 meta_s[MAX_NNZ];                           // 8 KB
    __shared__ int  row_s[DIM_OUT + 1];

    const int tid = threadIdx.x;

    // Stage 2 edges of x and y (edges are contiguous: 2*2048 floats each).
    {
        const float4* xg = (const float4*)x + (size_t)blockIdx.x * (2 * DIM_IN * CHANNELS / 4);
        const float4* yg = (const float4*)y + (size_t)blockIdx.x * (2 * DIM_IN * CHANNELS / 4);
        float4* xs4 = (float4*)xs;
        float4* ys4 = (float4*)ys;
#pragma unroll
        for (int i = 0; i < 8; i++) {
            xs4[tid + i * 128] = xg[tid + i * 128];
            ys4[tid + i * 128] = yg[tid + i * 128];
        }
    }
    for (int k = tid; k < nnz; k += 128) meta_s[k] = g_meta[k];
    for (int i = tid; i < DIM_OUT + 1; i += 128) row_s[i] = g_rowptr[i];
    __syncthreads();

    const int lt = tid & 63;   // float2 channel slot (0..63)
    const int e  = tid >> 6;   // which edge of the pair

    const float2* xe = (const float2*)xs + e * (DIM_IN * 64) + lt;
    const float2* ye = (const float2*)ys + e * (DIM_IN * 64) + lt;
    float2* op = (float2*)out + ((size_t)(blockIdx.x * 2 + e) * DIM_OUT) * 64 + lt;

    int k = 0;
#pragma unroll 1
    for (int m3 = 0; m3 < DIM_OUT; m3++) {
        const int ke = row_s[m3 + 1];
        float ax = 0.f, ay = 0.f;
        for (; k < ke; k++) {
            int2  me = meta_s[k];                    // warp-uniform broadcast
            float c  = __int_as_float(me.y);
            float2 xv = xe[(me.x >> 4) * 64];
            float2 yv = ye[(me.x & 15) * 64];
            ax = fmaf(c * xv.x, yv.x, ax);
            ay = fmaf(c * xv.y, yv.y, ay);
        }
        op[m3 * 64] = make_float2(ax, ay);
    }
}

// ---------------------------------------------------------------------------
extern "C" void kernel_launch(void* const* d_in, const int* in_sizes, int n_in,
                              void* d_out, int out_size)
{
    const float* x   = (const float*)d_in[0];
    const float* y   = (const float*)d_in[1];
    const int*   mu1 = (const int*)d_in[2];
    const int*   mu2 = (const int*)d_in[3];
    const int*   mu3 = (const int*)d_in[4];
    const float* cg  = (const float*)d_in[5];

    int nnz = in_sizes[2];
    if (nnz > MAX_NNZ) nnz = MAX_NNZ;
    int n_edges = in_sizes[0] / (DIM_IN * CHANNELS);

    tp_preprocess_kernel<<<1, 256>>>(mu1, mu2, mu3, cg, nnz);
    tp_main_kernel<<<n_edges / 2, 128>>>(x, y, (float*)d_out, nnz);
}

// round 4
// speedup vs baseline: 1.1411x; 1.1411x over previous
#include <cuda_runtime.h>
#include <cuda_bf16.h>
#include <cstdint>

#define DIM_IN   16
#define DIM_OUT  99
#define CHANNELS 128
#define MAX_NNZ  1024

// Scratch (allocation-free): CSR metadata sorted by output index m3.
// meta.x = (mu1*512) | (mu2*512 << 16)   (byte offsets into a 16x128 f32 edge tile)
// meta.y = float bits of cg
__device__ int2 g_meta[MAX_NNZ + 1];
__device__ int  g_rowptr[DIM_OUT + 1];

// ---------------------------------------------------------------------------
// Preprocess: build CSR grouped by mu3. Deterministic (rank-based stable
// scatter: position independent of atomic ordering).
// ---------------------------------------------------------------------------
__global__ void tp_preprocess_kernel(const int* __restrict__ mu1,
                                     const int* __restrict__ mu2,
                                     const int* __restrict__ mu3,
                                     const float* __restrict__ cg,
                                     int nnz)
{
    __shared__ int mu3s[MAX_NNZ];
    __shared__ int cnt[DIM_OUT + 1];
    __shared__ int row_s[DIM_OUT + 1];

    int tid = threadIdx.x;
    for (int i = tid; i < DIM_OUT + 1; i += blockDim.x) cnt[i] = 0;
    for (int k = tid; k < nnz; k += blockDim.x) mu3s[k] = mu3[k];
    __syncthreads();

    for (int k = tid; k < nnz; k += blockDim.x) atomicAdd(&cnt[mu3s[k]], 1);
    __syncthreads();

    if (tid == 0) {
        int run = 0;
        for (int i = 0; i < DIM_OUT; i++) { row_s[i] = run; run += cnt[i]; }
        row_s[DIM_OUT] = run;
    }
    __syncthreads();

    for (int i = tid; i < DIM_OUT + 1; i += blockDim.x) g_rowptr[i] = row_s[i];

    // Stable rank within its m3 group: count earlier entries with same m3.
    for (int k = tid; k < nnz; k += blockDim.x) {
        int m = mu3s[k];
        int r = 0;
        for (int j = 0; j < k; j++) r += (mu3s[j] == m) ? 1 : 0;
        int pos = row_s[m] + r;
        int xoff = mu1[k] * (CHANNELS * 4);           // byte offset of x row
        int yoff = mu2[k] * (CHANNELS * 4);           // byte offset of y row
        g_meta[pos] = make_int2(xoff | (yoff << 16), __float_as_int(cg[k]));
    }
    // sentinel (read by prefetch at k == nnz)
    if (tid == 0) g_meta[nnz] = make_int2(0, 0);
}

// ---------------------------------------------------------------------------
// Main kernel: 128 threads = 4 warps = 4 edges per block; each warp owns one
// edge, each thread 4 channels (float4). Operands staged in smem, packed
// f32x2 math, single f32x2 accumulator pair per output row (CSR order).
// ---------------------------------------------------------------------------
__global__ __launch_bounds__(128)
void tp_main_kernel(const float* __restrict__ x,
                    const float* __restrict__ y,
                    float* __restrict__ out,
                    int nnz)
{
    extern __shared__ __align__(16) char smem_raw[];
    float* xs    = (float*)smem_raw;                       // 4 * 2048 f32 = 32KB
    float* ys    = xs + 4 * DIM_IN * CHANNELS;             // 32KB
    int2*  metas = (int2*)(ys + 4 * DIM_IN * CHANNELS);    // 8KB + 8B
    int*   rows  = (int*)(metas + MAX_NNZ + 1);            // 400B

    const int tid = threadIdx.x;

    // Stage 4 edges of x and y (contiguous: 4*2048 floats = 2048 float4 each).
    {
        const float4* xg = (const float4*)x + (size_t)blockIdx.x * 2048;
        const float4* yg = (const float4*)y + (size_t)blockIdx.x * 2048;
        float4* xs4 = (float4*)xs;
        float4* ys4 = (float4*)ys;
#pragma unroll
        for (int i = 0; i < 16; i++) {
            xs4[tid + i * 128] = xg[tid + i * 128];
            ys4[tid + i * 128] = yg[tid + i * 128];
        }
    }
    for (int k = tid; k < nnz + 1; k += 128) metas[k] = g_meta[k];
    for (int i = tid; i < DIM_OUT + 1; i += 128) rows[i] = g_rowptr[i];
    __syncthreads();

    const int wid  = tid >> 5;        // edge within block
    const int lane = tid & 31;        // float4 channel slot (0..31)

    const uint32_t xb = (uint32_t)__cvta_generic_to_shared(xs) + wid * (DIM_IN * CHANNELS * 4) + lane * 16;
    const uint32_t yb = (uint32_t)__cvta_generic_to_shared(ys) + wid * (DIM_IN * CHANNELS * 4) + lane * 16;

    const size_t edge = (size_t)blockIdx.x * 4 + wid;
    float* op = out + edge * (DIM_OUT * CHANNELS) + lane * 4;

    int k = 0;
    int2 me = metas[0];
#pragma unroll 1
    for (int m3 = 0; m3 < DIM_OUT; m3++) {
        const int ke = rows[m3 + 1];
        uint64_t a0 = 0ull, a1 = 0ull;   // f32x2 accumulators {0.f,0.f}
#pragma unroll 1
        while (k < ke) {
            const int2 cur = me;
            k++;
            me = metas[k];               // prefetch next (sentinel-safe)

            uint32_t xo = (uint32_t)cur.x & 0xFFFFu;
            uint32_t yo = (uint32_t)cur.x >> 16;

            uint64_t cc;
            asm("mov.b64 %0, {%1, %1};" : "=l"(cc) : "r"(cur.y));

            uint64_t x0, x1, y0, y1;
            asm("ld.shared.v2.b64 {%0, %1}, [%2];" : "=l"(x0), "=l"(x1) : "r"(xb + xo));
            asm("ld.shared.v2.b64 {%0, %1}, [%2];" : "=l"(y0), "=l"(y1) : "r"(yb + yo));

            uint64_t p0, p1;
            asm("mul.rn.f32x2 %0, %1, %2;" : "=l"(p0) : "l"(x0), "l"(y0));
            asm("mul.rn.f32x2 %0, %1, %2;" : "=l"(p1) : "l"(x1), "l"(y1));
            asm("fma.rn.f32x2 %0, %1, %2, %3;" : "=l"(a0) : "l"(p0), "l"(cc), "l"(a0));
            asm("fma.rn.f32x2 %0, %1, %2, %3;" : "=l"(a1) : "l"(p1), "l"(cc), "l"(a1));
        }
        asm volatile("st.global.v2.b64 [%0], {%1, %2};"
                     :: "l"(op + m3 * CHANNELS), "l"(a0), "l"(a1) : "memory");
    }
}

// ---------------------------------------------------------------------------
extern "C" void kernel_launch(void* const* d_in, const int* in_sizes, int n_in,
                              void* d_out, int out_size)
{
    const float* x   = (const float*)d_in[0];
    const float* y   = (const float*)d_in[1];
    const int*   mu1 = (const int*)d_in[2];
    const int*   mu2 = (const int*)d_in[3];
    const int*   mu3 = (const int*)d_in[4];
    const float* cg  = (const float*)d_in[5];

    int nnz = in_sizes[2];
    if (nnz > MAX_NNZ) nnz = MAX_NNZ;
    int n_edges = in_sizes[0] / (DIM_IN * CHANNELS);

    const int smem_bytes = 4 * DIM_IN * CHANNELS * 4 * 2      // xs + ys
                         + (MAX_NNZ + 1) * 8                  // metas
                         + (DIM_OUT + 1) * 4 + 16;            // rows + pad
    static bool attr_ok = false;  // idempotent, same value every call
    cudaFuncSetAttribute(tp_main_kernel,
                         cudaFuncAttributeMaxDynamicSharedMemorySize, smem_bytes);
    (void)attr_ok;

    tp_preprocess_kernel<<<1, 256>>>(mu1, mu2, mu3, cg, nnz);
    tp_main_kernel<<<n_edges / 4, 128, smem_bytes>>>(x, y, (float*)d_out, nnz);
}